// round 10
// baseline (speedup 1.0000x reference)
#include <cuda_runtime.h>
#include <cuda_bf16.h>
#include <cstdint>
#include <math.h>

// ============================================================
// bf16-split GEMM per layer via mma.sync (HMMA).
//   layer i: out[c,j] = tanh( sum_k W[c,k]*B[k,j] + bias[c] )
//   B[k][j] = in[k>>1][2j + (k&1)]   (compacted dilated conv)
//   fp32 ~= bf16 hi+lo:  A*B ~= Ah*Bh + Ah*Bl + Al*Bh
// Activations carried between layers as bf16 hi/lo planes.
// R10: R9 structure with
//   - BK=64 (8 chunks instead of 16): fewer barriers/serial deps
//   - no reg prefetch; __launch_bounds__(256,2) -> 2 CTAs/SM,
//     cross-CTA overlap hides global-load latency
//   - dynamic smem (72KB/CTA)
// ============================================================

#define RS 144   // smem row stride in bytes (128B payload + 16 pad)

#define OFF_AH 0
#define OFF_AL 18432
#define OFF_BH 36864
#define OFF_BL 55296
#define SMEM_TOTAL 73728

// ---------------- scratch ----------------
__device__ __nv_bfloat16 g_ahi[256 * 32768];
__device__ __nv_bfloat16 g_alo[256 * 32768];
__device__ __nv_bfloat16 g_bhi[256 * 16384];
__device__ __nv_bfloat16 g_blo[256 * 16384];
__device__ __nv_bfloat16 g_whi[16 * 256 * 512];
__device__ __nv_bfloat16 g_wlo[16 * 256 * 512];

// ---------------- helpers ----------------
__device__ __forceinline__ void ldsm_x4(uint32_t* r, uint32_t addr) {
    asm volatile("ldmatrix.sync.aligned.m8n8.x4.shared.b16 {%0,%1,%2,%3}, [%4];"
        : "=r"(r[0]), "=r"(r[1]), "=r"(r[2]), "=r"(r[3]) : "r"(addr));
}

__device__ __forceinline__ void mma_bf16(float* c, const uint32_t* a, const uint32_t* b) {
    asm volatile(
        "mma.sync.aligned.m16n8k16.row.col.f32.bf16.bf16.f32 "
        "{%0,%1,%2,%3}, {%4,%5,%6,%7}, {%8,%9}, {%0,%1,%2,%3};"
        : "+f"(c[0]), "+f"(c[1]), "+f"(c[2]), "+f"(c[3])
        : "r"(a[0]), "r"(a[1]), "r"(a[2]), "r"(a[3]), "r"(b[0]), "r"(b[1]));
}

__device__ __forceinline__ void split2(float x, float y, uint32_t& h, uint32_t& l) {
    __nv_bfloat16 hx = __float2bfloat16(x);
    __nv_bfloat16 hy = __float2bfloat16(y);
    __nv_bfloat162 hp; hp.x = hx; hp.y = hy;
    __nv_bfloat162 lp;
    lp.x = __float2bfloat16(x - __bfloat162float(hx));
    lp.y = __float2bfloat16(y - __bfloat162float(hy));
    h = *reinterpret_cast<uint32_t*>(&hp);
    l = *reinterpret_cast<uint32_t*>(&lp);
}

// ---------------- weight hi/lo split ----------------
__global__ void prep_w(const float* __restrict__ W,
                       __nv_bfloat16* __restrict__ hi,
                       __nv_bfloat16* __restrict__ lo, int n) {
    int i = blockIdx.x * blockDim.x + threadIdx.x;
    if (i < n) {
        float v = W[i];
        __nv_bfloat16 h = __float2bfloat16(v);
        hi[i] = h;
        lo[i] = __float2bfloat16(v - __bfloat162float(h));
    }
}

// ---------------- per-layer GEMM kernel ----------------
// CTA: 256 threads = 8 warps in 2(M) x 4(N); tile 128x128, BK=64, 8 chunks.
__global__ __launch_bounds__(256, 2) void layer_hmma(
    const void* __restrict__ in_hi,          // bf16 plane, or fp32 if fp32_in
    const __nv_bfloat16* __restrict__ in_lo,
    const __nv_bfloat16* __restrict__ Whi,   // 256 x 512
    const __nv_bfloat16* __restrict__ Wlo,
    const float* __restrict__ bias,          // 256
    __nv_bfloat16* __restrict__ out_hi,      // 256 x Nout
    __nv_bfloat16* __restrict__ out_lo,
    float* __restrict__ out_f,               // non-null on final layer
    int Nin, int Nout, int fp32_in)
{
    extern __shared__ __align__(16) char smem[];
    char* sAh = smem + OFF_AH;
    char* sAl = smem + OFF_AL;
    char* sBh = smem + OFF_BH;
    char* sBl = smem + OFF_BL;

    const int tid  = threadIdx.x;
    const int lane = tid & 31;
    const int wid  = tid >> 5;
    const int wm   = wid & 1;     // 0..1 : 64-row slab
    const int wn   = wid >> 1;    // 0..3 : 32-col slab
    const int m0   = blockIdx.y * 128;
    const int j0   = blockIdx.x * 128;

    float acc[4][4][4];
    #pragma unroll
    for (int a = 0; a < 4; a++)
        #pragma unroll
        for (int b = 0; b < 4; b++)
            #pragma unroll
            for (int c = 0; c < 4; c++) acc[a][b][c] = 0.f;

    const uint32_t sAh_u = (uint32_t)__cvta_generic_to_shared(sAh);
    const uint32_t sAl_u = (uint32_t)__cvta_generic_to_shared(sAl);
    const uint32_t sBh_u = (uint32_t)__cvta_generic_to_shared(sBh);
    const uint32_t sBl_u = (uint32_t)__cvta_generic_to_shared(sBl);

    // ldmatrix per-lane source rows (verified mapping)
    const int a_row = lane & 15;
    const int a_cb  = lane >> 4;
    const int b_row = (lane & 7) + ((lane >> 4) << 3);
    const int b_cb  = (lane >> 3) & 1;

    // loader mapping
    const int l_arow = tid >> 1, l_ahalf = tid & 1;   // A: 128 rows x 2 64B-halves
    const int l_c = tid & 31, l_seg = tid >> 5;       // B: 32 chans x 8 segments

    for (int chunk = 0; chunk < 8; chunk++) {
        const int k0 = chunk * 64;

        // ---- A tile: 128 x 64 bf16 (hi & lo) ----
        {
            size_t gofs = (size_t)(m0 + l_arow) * 512 + k0 + l_ahalf * 32;
            const uint4* ph = reinterpret_cast<const uint4*>(Whi + gofs);
            const uint4* pl = reinterpret_cast<const uint4*>(Wlo + gofs);
            char* dh = sAh + l_arow * RS + l_ahalf * 64;
            char* dl = sAl + l_arow * RS + l_ahalf * 64;
            #pragma unroll
            for (int q = 0; q < 4; q++) {
                reinterpret_cast<uint4*>(dh)[q] = ph[q];
                reinterpret_cast<uint4*>(dl)[q] = pl[q];
            }
        }

        // ---- B tile: sB[j][k], j=128 rows, k=64 cols ----
        // thread: channel l_c (of 32), times t..t+31 -> rows l_seg*16..+15, cols 2*l_c,2*l_c+1
        {
            const int ch = (k0 >> 1) + l_c;
            const int t  = 2 * j0 + l_seg * 32;
            uint32_t wh[16], wl[16];
            if (fp32_in) {
                const float* p = reinterpret_cast<const float*>(in_hi) + (size_t)ch * Nin + t;
                if (t + 31 < Nin) {
                    #pragma unroll
                    for (int q = 0; q < 8; q++) {
                        float4 f = reinterpret_cast<const float4*>(p)[q];
                        split2(f.x, f.y, wh[2 * q],     wl[2 * q]);
                        split2(f.z, f.w, wh[2 * q + 1], wl[2 * q + 1]);
                    }
                } else {
                    #pragma unroll
                    for (int v = 0; v < 16; v++) {
                        float f0 = (t + 2 * v     < Nin) ? p[2 * v]     : 0.f;
                        float f1 = (t + 2 * v + 1 < Nin) ? p[2 * v + 1] : 0.f;
                        split2(f0, f1, wh[v], wl[v]);
                    }
                }
            } else {
                const __nv_bfloat16* ph = reinterpret_cast<const __nv_bfloat16*>(in_hi) + (size_t)ch * Nin + t;
                const __nv_bfloat16* pl = in_lo + (size_t)ch * Nin + t;
                if (t + 31 < Nin) {
                    #pragma unroll
                    for (int q = 0; q < 4; q++) {
                        uint4 uh = reinterpret_cast<const uint4*>(ph)[q];
                        uint4 ul = reinterpret_cast<const uint4*>(pl)[q];
                        wh[4 * q + 0] = uh.x; wh[4 * q + 1] = uh.y;
                        wh[4 * q + 2] = uh.z; wh[4 * q + 3] = uh.w;
                        wl[4 * q + 0] = ul.x; wl[4 * q + 1] = ul.y;
                        wl[4 * q + 2] = ul.z; wl[4 * q + 3] = ul.w;
                    }
                } else {
                    #pragma unroll
                    for (int v = 0; v < 16; v++) {
                        __nv_bfloat162 hp, lp;
                        hp.x = (t + 2 * v     < Nin) ? ph[2 * v]     : __nv_bfloat16(0.f);
                        hp.y = (t + 2 * v + 1 < Nin) ? ph[2 * v + 1] : __nv_bfloat16(0.f);
                        lp.x = (t + 2 * v     < Nin) ? pl[2 * v]     : __nv_bfloat16(0.f);
                        lp.y = (t + 2 * v + 1 < Nin) ? pl[2 * v + 1] : __nv_bfloat16(0.f);
                        wh[v] = *reinterpret_cast<uint32_t*>(&hp);
                        wl[v] = *reinterpret_cast<uint32_t*>(&lp);
                    }
                }
            }
            char* dbh = sBh + (l_seg * 16) * RS + 4 * l_c;
            char* dbl = sBl + (l_seg * 16) * RS + 4 * l_c;
            #pragma unroll
            for (int v = 0; v < 16; v++) {
                *reinterpret_cast<uint32_t*>(dbh + v * RS) = wh[v];
                *reinterpret_cast<uint32_t*>(dbl + v * RS) = wl[v];
            }
        }
        __syncthreads();

        // ---- compute: 4 k16 steps x (AhBh + AhBl + AlBh) ----
        #pragma unroll
        for (int ks = 0; ks < 4; ks++) {
            uint32_t af[4][4], bh[4][2], bl[4][2];
            #pragma unroll
            for (int mt = 0; mt < 4; mt++) {
                uint32_t ofs = (uint32_t)((wm * 64 + mt * 16 + a_row) * RS + ks * 32 + a_cb * 16);
                ldsm_x4(af[mt], sAh_u + ofs);
            }
            #pragma unroll
            for (int half = 0; half < 2; half++) {
                uint32_t ofs = (uint32_t)((wn * 32 + half * 16 + b_row) * RS + ks * 32 + b_cb * 16);
                uint32_t r[4];
                ldsm_x4(r, sBh_u + ofs);
                bh[half * 2][0] = r[0]; bh[half * 2][1] = r[1];
                bh[half * 2 + 1][0] = r[2]; bh[half * 2 + 1][1] = r[3];
                ldsm_x4(r, sBl_u + ofs);
                bl[half * 2][0] = r[0]; bl[half * 2][1] = r[1];
                bl[half * 2 + 1][0] = r[2]; bl[half * 2 + 1][1] = r[3];
            }
            #pragma unroll
            for (int mt = 0; mt < 4; mt++)
                #pragma unroll
                for (int nt = 0; nt < 4; nt++) {
                    mma_bf16(acc[mt][nt], af[mt], bh[nt]);
                    mma_bf16(acc[mt][nt], af[mt], bl[nt]);
                }
            #pragma unroll
            for (int mt = 0; mt < 4; mt++) {
                uint32_t ofs = (uint32_t)((wm * 64 + mt * 16 + a_row) * RS + ks * 32 + a_cb * 16);
                ldsm_x4(af[mt], sAl_u + ofs);
            }
            #pragma unroll
            for (int mt = 0; mt < 4; mt++)
                #pragma unroll
                for (int nt = 0; nt < 4; nt++)
                    mma_bf16(acc[mt][nt], af[mt], bh[nt]);
        }
        __syncthreads();
    }

    // ---- epilogue: bias + tanh; write bf16 hi/lo planes (or fp32 final) ----
    const int g = lane >> 2, tig = lane & 3;
    #pragma unroll
    for (int mt = 0; mt < 4; mt++) {
        const int mA = m0 + wm * 64 + mt * 16 + g;
        const int mB = mA + 8;
        const float bA = bias[mA], bB = bias[mB];
        #pragma unroll
        for (int nt = 0; nt < 4; nt++) {
            const int col = j0 + wn * 32 + nt * 8 + 2 * tig;
            float v0 = tanhf(acc[mt][nt][0] + bA);
            float v1 = tanhf(acc[mt][nt][1] + bA);
            float v2 = tanhf(acc[mt][nt][2] + bB);
            float v3 = tanhf(acc[mt][nt][3] + bB);
            if (out_f) {
                if (col == 0) { out_f[mA] = v0; out_f[mB] = v2; }
            } else if (col < Nout) {
                uint32_t h, l;
                split2(v0, v1, h, l);
                *reinterpret_cast<uint32_t*>(out_hi + (size_t)mA * Nout + col) = h;
                *reinterpret_cast<uint32_t*>(out_lo + (size_t)mA * Nout + col) = l;
                split2(v2, v3, h, l);
                *reinterpret_cast<uint32_t*>(out_hi + (size_t)mB * Nout + col) = h;
                *reinterpret_cast<uint32_t*>(out_lo + (size_t)mB * Nout + col) = l;
            }
        }
    }
}

// ---------------- host ----------------
extern "C" void kernel_launch(void* const* d_in, const int* in_sizes, int n_in,
                              void* d_out, int out_size)
{
    const float* x = (const float*)d_in[0];   // (1, 256, 65536)
    const float* W = (const float*)d_in[1];   // (16, 256, 256, 2)
    const float* b = (const float*)d_in[2];   // (16, 256)

    __nv_bfloat16 *ahi, *alo, *bhi, *blo, *whi, *wlo;
    cudaGetSymbolAddress((void**)&ahi, g_ahi);
    cudaGetSymbolAddress((void**)&alo, g_alo);
    cudaGetSymbolAddress((void**)&bhi, g_bhi);
    cudaGetSymbolAddress((void**)&blo, g_blo);
    cudaGetSymbolAddress((void**)&whi, g_whi);
    cudaGetSymbolAddress((void**)&wlo, g_wlo);

    cudaFuncSetAttribute(layer_hmma, cudaFuncAttributeMaxDynamicSharedMemorySize, SMEM_TOTAL);

    const int nW = 16 * 256 * 512;
    prep_w<<<(nW + 255) / 256, 256>>>(W, whi, wlo, nW);

    int Nin = 65536;
    const void* cur_hi = (const void*)x;
    const __nv_bfloat16* cur_lo = nullptr;
    int fp32_in = 1;

    for (int i = 0; i < 16; i++) {
        int Nout = Nin >> 1;
        __nv_bfloat16* ohi = (i & 1) ? bhi : ahi;
        __nv_bfloat16* olo = (i & 1) ? blo : alo;
        float* of = (i == 15) ? (float*)d_out : nullptr;
        dim3 grid((Nout + 127) / 128, 2);
        layer_hmma<<<grid, 256, SMEM_TOTAL>>>(cur_hi, cur_lo,
                                  whi + (size_t)i * 256 * 512,
                                  wlo + (size_t)i * 256 * 512,
                                  b + i * 256,
                                  ohi, olo, of, Nin, Nout, fp32_in);
        cur_hi = (const void*)ohi;
        cur_lo = olo;
        fp32_in = 0;
        Nin = Nout;
    }
}

// round 11
// speedup vs baseline: 1.1709x; 1.1709x over previous
#include <cuda_runtime.h>
#include <cuda_bf16.h>
#include <cstdint>
#include <math.h>

// ============================================================
// bf16-split GEMM per layer via mma.sync (HMMA).
//   layer i: out[c,j] = tanh( sum_k W[c,k]*B[k,j] + bias[c] )
//   B[k][j] = in[k>>1][2j + (k&1)]   (compacted dilated conv)
//   fp32 ~= bf16 hi+lo:  A*B ~= Ah*Bh + Ah*Bl + Al*Bh
// Activations carried between layers as bf16 hi/lo planes.
// R11: R9 structure (register-prefetch double buffering, BK=32)
//      templated on N-tile: NT=128 (layers 0-1), NT=64 (2-15)
//      -> halves per-CTA latency and doubles grid for the
//         latency-bound small layers.
// ============================================================

#define RS 80   // smem row stride in bytes (64B payload + pad)

// ---------------- scratch ----------------
__device__ __nv_bfloat16 g_ahi[256 * 32768];
__device__ __nv_bfloat16 g_alo[256 * 32768];
__device__ __nv_bfloat16 g_bhi[256 * 16384];
__device__ __nv_bfloat16 g_blo[256 * 16384];
__device__ __nv_bfloat16 g_whi[16 * 256 * 512];
__device__ __nv_bfloat16 g_wlo[16 * 256 * 512];

// ---------------- helpers ----------------
__device__ __forceinline__ void ldsm_x4(uint32_t* r, uint32_t addr) {
    asm volatile("ldmatrix.sync.aligned.m8n8.x4.shared.b16 {%0,%1,%2,%3}, [%4];"
        : "=r"(r[0]), "=r"(r[1]), "=r"(r[2]), "=r"(r[3]) : "r"(addr));
}

__device__ __forceinline__ void mma_bf16(float* c, const uint32_t* a, const uint32_t* b) {
    asm volatile(
        "mma.sync.aligned.m16n8k16.row.col.f32.bf16.bf16.f32 "
        "{%0,%1,%2,%3}, {%4,%5,%6,%7}, {%8,%9}, {%0,%1,%2,%3};"
        : "+f"(c[0]), "+f"(c[1]), "+f"(c[2]), "+f"(c[3])
        : "r"(a[0]), "r"(a[1]), "r"(a[2]), "r"(a[3]), "r"(b[0]), "r"(b[1]));
}

__device__ __forceinline__ void split2(float x, float y, uint32_t& h, uint32_t& l) {
    __nv_bfloat16 hx = __float2bfloat16(x);
    __nv_bfloat16 hy = __float2bfloat16(y);
    __nv_bfloat162 hp; hp.x = hx; hp.y = hy;
    __nv_bfloat162 lp;
    lp.x = __float2bfloat16(x - __bfloat162float(hx));
    lp.y = __float2bfloat16(y - __bfloat162float(hy));
    h = *reinterpret_cast<uint32_t*>(&hp);
    l = *reinterpret_cast<uint32_t*>(&lp);
}

// ---------------- weight hi/lo split ----------------
__global__ void prep_w(const float* __restrict__ W,
                       __nv_bfloat16* __restrict__ hi,
                       __nv_bfloat16* __restrict__ lo, int n) {
    int i = blockIdx.x * blockDim.x + threadIdx.x;
    if (i < n) {
        float v = W[i];
        __nv_bfloat16 h = __float2bfloat16(v);
        hi[i] = h;
        lo[i] = __float2bfloat16(v - __bfloat162float(h));
    }
}

// ---------------- per-layer GEMM kernel ----------------
// CTA: 256 threads = 8 warps in 2(M) x 4(N) grid; tile 128 x NT, BK=32.
// NT=128: per-warp 4x4 acc tiles. NT=64: per-warp 4x2.
template<int NT>
__global__ __launch_bounds__(256) void layer_hmma(
    const void* __restrict__ in_hi,          // bf16 plane, or fp32 if fp32_in
    const __nv_bfloat16* __restrict__ in_lo,
    const __nv_bfloat16* __restrict__ Whi,   // 256 x 512
    const __nv_bfloat16* __restrict__ Wlo,
    const float* __restrict__ bias,          // 256
    __nv_bfloat16* __restrict__ out_hi,      // 256 x Nout
    __nv_bfloat16* __restrict__ out_lo,
    float* __restrict__ out_f,               // non-null on final layer
    int Nin, int Nout, int fp32_in)
{
    constexpr int NTT  = NT / 32;            // nt tiles per warp (4 or 2)
    constexpr int NHALF = NT / 64;           // 16-col B slabs per warp (2 or 1)
    constexpr int SEGT = NT / 8;             // times per loader thread (16 or 8)

    __shared__ __align__(16) char sAh[128 * RS];
    __shared__ __align__(16) char sAl[128 * RS];
    __shared__ __align__(16) char sBh[NT * RS];
    __shared__ __align__(16) char sBl[NT * RS];

    const int tid  = threadIdx.x;
    const int lane = tid & 31;
    const int wid  = tid >> 5;
    const int wm   = wid & 1;     // 0..1 : 64-row slab
    const int wn   = wid >> 1;    // 0..3 : NT/4-col slab
    const int m0   = blockIdx.y * 128;
    const int j0   = blockIdx.x * NT;

    float acc[4][NTT][4];
    #pragma unroll
    for (int a = 0; a < 4; a++)
        #pragma unroll
        for (int b = 0; b < NTT; b++)
            #pragma unroll
            for (int c = 0; c < 4; c++) acc[a][b][c] = 0.f;

    const uint32_t sAh_u = (uint32_t)__cvta_generic_to_shared(sAh);
    const uint32_t sAl_u = (uint32_t)__cvta_generic_to_shared(sAl);
    const uint32_t sBh_u = (uint32_t)__cvta_generic_to_shared(sBh);
    const uint32_t sBl_u = (uint32_t)__cvta_generic_to_shared(sBl);

    // ldmatrix per-lane source rows (verified mapping)
    const int a_row = lane & 15;
    const int a_cb  = lane >> 4;
    const int b_row = (lane & 7) + ((lane >> 4) << 3);
    const int b_cb  = (lane >> 3) & 1;

    // loader mapping
    const int l_arow = tid >> 1, l_ahalf = tid & 1;   // A: 128 rows x 2 halves
    const int l_c = tid & 15, l_seg = tid >> 4;       // B: 16 chans x 16 segments

    // ---- persistent prefetch registers ----
    uint4 pAh0, pAh1, pAl0, pAl1;
    uint32_t pBh[SEGT / 2], pBl[SEGT / 2];

    auto load_g = [&](int chunk) {
        const int k0 = chunk * 32;
        // A: 128 x 32 bf16 (hi & lo)
        {
            size_t gofs = (size_t)(m0 + l_arow) * 512 + k0 + l_ahalf * 16;
            const uint4* ph = reinterpret_cast<const uint4*>(Whi + gofs);
            const uint4* pl = reinterpret_cast<const uint4*>(Wlo + gofs);
            pAh0 = ph[0]; pAh1 = ph[1];
            pAl0 = pl[0]; pAl1 = pl[1];
        }
        // B: SEGT consecutive times per thread
        {
            const int ch = (k0 >> 1) + l_c;
            const int t  = 2 * j0 + l_seg * SEGT;
            if (fp32_in) {
                const float* p = reinterpret_cast<const float*>(in_hi) + (size_t)ch * Nin + t;
                if (t + SEGT - 1 < Nin) {
                    #pragma unroll
                    for (int q = 0; q < SEGT / 4; q++) {
                        float4 f = reinterpret_cast<const float4*>(p)[q];
                        split2(f.x, f.y, pBh[2 * q],     pBl[2 * q]);
                        split2(f.z, f.w, pBh[2 * q + 1], pBl[2 * q + 1]);
                    }
                } else {
                    #pragma unroll
                    for (int q = 0; q < SEGT / 2; q++) {
                        float f0 = (t + 2 * q     < Nin) ? p[2 * q]     : 0.f;
                        float f1 = (t + 2 * q + 1 < Nin) ? p[2 * q + 1] : 0.f;
                        split2(f0, f1, pBh[q], pBl[q]);
                    }
                }
            } else {
                const __nv_bfloat16* ph = reinterpret_cast<const __nv_bfloat16*>(in_hi) + (size_t)ch * Nin + t;
                const __nv_bfloat16* pl = in_lo + (size_t)ch * Nin + t;
                if (t + SEGT - 1 < Nin) {
                    #pragma unroll
                    for (int q = 0; q < SEGT / 8; q++) {
                        uint4 uh = reinterpret_cast<const uint4*>(ph)[q];
                        uint4 ul = reinterpret_cast<const uint4*>(pl)[q];
                        pBh[4 * q + 0] = uh.x; pBh[4 * q + 1] = uh.y;
                        pBh[4 * q + 2] = uh.z; pBh[4 * q + 3] = uh.w;
                        pBl[4 * q + 0] = ul.x; pBl[4 * q + 1] = ul.y;
                        pBl[4 * q + 2] = ul.z; pBl[4 * q + 3] = ul.w;
                    }
                } else {
                    #pragma unroll
                    for (int q = 0; q < SEGT / 2; q++) {
                        __nv_bfloat162 hp, lp;
                        hp.x = (t + 2 * q     < Nin) ? ph[2 * q]     : __nv_bfloat16(0.f);
                        hp.y = (t + 2 * q + 1 < Nin) ? ph[2 * q + 1] : __nv_bfloat16(0.f);
                        lp.x = (t + 2 * q     < Nin) ? pl[2 * q]     : __nv_bfloat16(0.f);
                        lp.y = (t + 2 * q + 1 < Nin) ? pl[2 * q + 1] : __nv_bfloat16(0.f);
                        pBh[q] = *reinterpret_cast<uint32_t*>(&hp);
                        pBl[q] = *reinterpret_cast<uint32_t*>(&lp);
                    }
                }
            }
        }
    };

    auto store_smem = [&]() {
        char* dh = sAh + l_arow * RS + l_ahalf * 32;
        char* dl = sAl + l_arow * RS + l_ahalf * 32;
        reinterpret_cast<uint4*>(dh)[0] = pAh0;
        reinterpret_cast<uint4*>(dh)[1] = pAh1;
        reinterpret_cast<uint4*>(dl)[0] = pAl0;
        reinterpret_cast<uint4*>(dl)[1] = pAl1;
        char* dbh = sBh + (l_seg * (SEGT / 2)) * RS + 4 * l_c;
        char* dbl = sBl + (l_seg * (SEGT / 2)) * RS + 4 * l_c;
        #pragma unroll
        for (int q = 0; q < SEGT / 2; q++) {
            *reinterpret_cast<uint32_t*>(dbh + q * RS) = pBh[q];
            *reinterpret_cast<uint32_t*>(dbl + q * RS) = pBl[q];
        }
    };

    load_g(0);
    for (int chunk = 0; chunk < 16; chunk++) {
        store_smem();
        __syncthreads();
        if (chunk + 1 < 16) load_g(chunk + 1);   // LDGs in flight during compute

        // ---- compute: 2 k16 steps x (AhBh + AhBl + AlBh) ----
        #pragma unroll
        for (int ks = 0; ks < 2; ks++) {
            uint32_t af[4][4], bh[NTT][2], bl[NTT][2];
            #pragma unroll
            for (int mt = 0; mt < 4; mt++) {
                uint32_t ofs = (uint32_t)((wm * 64 + mt * 16 + a_row) * RS + ks * 32 + a_cb * 16);
                ldsm_x4(af[mt], sAh_u + ofs);
            }
            #pragma unroll
            for (int half = 0; half < NHALF; half++) {
                uint32_t ofs = (uint32_t)((wn * (NT / 4) + half * 16 + b_row) * RS + ks * 32 + b_cb * 16);
                uint32_t r[4];
                ldsm_x4(r, sBh_u + ofs);
                bh[half * 2][0] = r[0]; bh[half * 2][1] = r[1];
                bh[half * 2 + 1][0] = r[2]; bh[half * 2 + 1][1] = r[3];
                ldsm_x4(r, sBl_u + ofs);
                bl[half * 2][0] = r[0]; bl[half * 2][1] = r[1];
                bl[half * 2 + 1][0] = r[2]; bl[half * 2 + 1][1] = r[3];
            }
            #pragma unroll
            for (int mt = 0; mt < 4; mt++)
                #pragma unroll
                for (int nt = 0; nt < NTT; nt++) {
                    mma_bf16(acc[mt][nt], af[mt], bh[nt]);
                    mma_bf16(acc[mt][nt], af[mt], bl[nt]);
                }
            #pragma unroll
            for (int mt = 0; mt < 4; mt++) {
                uint32_t ofs = (uint32_t)((wm * 64 + mt * 16 + a_row) * RS + ks * 32 + a_cb * 16);
                ldsm_x4(af[mt], sAl_u + ofs);
            }
            #pragma unroll
            for (int mt = 0; mt < 4; mt++)
                #pragma unroll
                for (int nt = 0; nt < NTT; nt++)
                    mma_bf16(acc[mt][nt], af[mt], bh[nt]);
        }
        __syncthreads();
    }

    // ---- epilogue: bias + tanh; write bf16 hi/lo planes (or fp32 final) ----
    const int g = lane >> 2, tig = lane & 3;
    #pragma unroll
    for (int mt = 0; mt < 4; mt++) {
        const int mA = m0 + wm * 64 + mt * 16 + g;
        const int mB = mA + 8;
        const float bA = bias[mA], bB = bias[mB];
        #pragma unroll
        for (int nt = 0; nt < NTT; nt++) {
            const int col = j0 + wn * (NT / 4) + nt * 8 + 2 * tig;
            float v0 = tanhf(acc[mt][nt][0] + bA);
            float v1 = tanhf(acc[mt][nt][1] + bA);
            float v2 = tanhf(acc[mt][nt][2] + bB);
            float v3 = tanhf(acc[mt][nt][3] + bB);
            if (out_f) {
                if (col == 0) { out_f[mA] = v0; out_f[mB] = v2; }
            } else if (col < Nout) {
                uint32_t h, l;
                split2(v0, v1, h, l);
                *reinterpret_cast<uint32_t*>(out_hi + (size_t)mA * Nout + col) = h;
                *reinterpret_cast<uint32_t*>(out_lo + (size_t)mA * Nout + col) = l;
                split2(v2, v3, h, l);
                *reinterpret_cast<uint32_t*>(out_hi + (size_t)mB * Nout + col) = h;
                *reinterpret_cast<uint32_t*>(out_lo + (size_t)mB * Nout + col) = l;
            }
        }
    }
}

// ---------------- host ----------------
extern "C" void kernel_launch(void* const* d_in, const int* in_sizes, int n_in,
                              void* d_out, int out_size)
{
    const float* x = (const float*)d_in[0];   // (1, 256, 65536)
    const float* W = (const float*)d_in[1];   // (16, 256, 256, 2)
    const float* b = (const float*)d_in[2];   // (16, 256)

    __nv_bfloat16 *ahi, *alo, *bhi, *blo, *whi, *wlo;
    cudaGetSymbolAddress((void**)&ahi, g_ahi);
    cudaGetSymbolAddress((void**)&alo, g_alo);
    cudaGetSymbolAddress((void**)&bhi, g_bhi);
    cudaGetSymbolAddress((void**)&blo, g_blo);
    cudaGetSymbolAddress((void**)&whi, g_whi);
    cudaGetSymbolAddress((void**)&wlo, g_wlo);

    const int nW = 16 * 256 * 512;
    prep_w<<<(nW + 255) / 256, 256>>>(W, whi, wlo, nW);

    int Nin = 65536;
    const void* cur_hi = (const void*)x;
    const __nv_bfloat16* cur_lo = nullptr;
    int fp32_in = 1;

    for (int i = 0; i < 16; i++) {
        int Nout = Nin >> 1;
        __nv_bfloat16* ohi = (i & 1) ? bhi : ahi;
        __nv_bfloat16* olo = (i & 1) ? blo : alo;
        float* of = (i == 15) ? (float*)d_out : nullptr;
        if (Nout >= 16384) {
            dim3 grid((Nout + 127) / 128, 2);
            layer_hmma<128><<<grid, 256>>>(cur_hi, cur_lo,
                                      whi + (size_t)i * 256 * 512,
                                      wlo + (size_t)i * 256 * 512,
                                      b + i * 256,
                                      ohi, olo, of, Nin, Nout, fp32_in);
        } else {
            dim3 grid((Nout + 63) / 64, 2);
            layer_hmma<64><<<grid, 256>>>(cur_hi, cur_lo,
                                      whi + (size_t)i * 256 * 512,
                                      wlo + (size_t)i * 256 * 512,
                                      b + i * 256,
                                      ohi, olo, of, Nin, Nout, fp32_in);
        }
        cur_hi = (const void*)ohi;
        cur_lo = olo;
        fp32_in = 0;
        Nin = Nout;
    }
}

// round 12
// speedup vs baseline: 1.2045x; 1.0287x over previous
#include <cuda_runtime.h>
#include <cuda_bf16.h>
#include <cstdint>
#include <math.h>

// ============================================================
// bf16-split GEMM per layer via mma.sync (HMMA).
//   layer i: out[c,j] = tanh( sum_k W[c,k]*B[k,j] + bias[c] )
//   B[k][j] = in[k>>1][2j + (k&1)]   (compacted dilated conv)
//   fp32 ~= bf16 hi+lo:  A*B ~= Ah*Bh + Ah*Bl + Al*Bh
// R12: R11 + double-buffered smem (ONE barrier per chunk) and
//      hoisted ldsm per ks-step. Register prefetch retained.
// ============================================================

#define RS 80   // smem row stride in bytes (64B payload + pad)
#define ASZ (128 * RS)          // one A buffer (10240 B)

// ---------------- scratch ----------------
__device__ __nv_bfloat16 g_ahi[256 * 32768];
__device__ __nv_bfloat16 g_alo[256 * 32768];
__device__ __nv_bfloat16 g_bhi[256 * 16384];
__device__ __nv_bfloat16 g_blo[256 * 16384];
__device__ __nv_bfloat16 g_whi[16 * 256 * 512];
__device__ __nv_bfloat16 g_wlo[16 * 256 * 512];

// ---------------- helpers ----------------
__device__ __forceinline__ void ldsm_x4(uint32_t* r, uint32_t addr) {
    asm volatile("ldmatrix.sync.aligned.m8n8.x4.shared.b16 {%0,%1,%2,%3}, [%4];"
        : "=r"(r[0]), "=r"(r[1]), "=r"(r[2]), "=r"(r[3]) : "r"(addr));
}

__device__ __forceinline__ void mma_bf16(float* c, const uint32_t* a, const uint32_t* b) {
    asm volatile(
        "mma.sync.aligned.m16n8k16.row.col.f32.bf16.bf16.f32 "
        "{%0,%1,%2,%3}, {%4,%5,%6,%7}, {%8,%9}, {%0,%1,%2,%3};"
        : "+f"(c[0]), "+f"(c[1]), "+f"(c[2]), "+f"(c[3])
        : "r"(a[0]), "r"(a[1]), "r"(a[2]), "r"(a[3]), "r"(b[0]), "r"(b[1]));
}

__device__ __forceinline__ void split2(float x, float y, uint32_t& h, uint32_t& l) {
    __nv_bfloat16 hx = __float2bfloat16(x);
    __nv_bfloat16 hy = __float2bfloat16(y);
    __nv_bfloat162 hp; hp.x = hx; hp.y = hy;
    __nv_bfloat162 lp;
    lp.x = __float2bfloat16(x - __bfloat162float(hx));
    lp.y = __float2bfloat16(y - __bfloat162float(hy));
    h = *reinterpret_cast<uint32_t*>(&hp);
    l = *reinterpret_cast<uint32_t*>(&lp);
}

// ---------------- weight hi/lo split ----------------
__global__ void prep_w(const float* __restrict__ W,
                       __nv_bfloat16* __restrict__ hi,
                       __nv_bfloat16* __restrict__ lo, int n) {
    int i = blockIdx.x * blockDim.x + threadIdx.x;
    if (i < n) {
        float v = W[i];
        __nv_bfloat16 h = __float2bfloat16(v);
        hi[i] = h;
        lo[i] = __float2bfloat16(v - __bfloat162float(h));
    }
}

// ---------------- per-layer GEMM kernel ----------------
// CTA: 256 threads = 8 warps in 2(M) x 4(N); tile 128 x NT, BK=32.
// Double-buffered smem; one __syncthreads per chunk.
template<int NT>
__global__ __launch_bounds__(256) void layer_hmma(
    const void* __restrict__ in_hi,
    const __nv_bfloat16* __restrict__ in_lo,
    const __nv_bfloat16* __restrict__ Whi,   // 256 x 512
    const __nv_bfloat16* __restrict__ Wlo,
    const float* __restrict__ bias,
    __nv_bfloat16* __restrict__ out_hi,
    __nv_bfloat16* __restrict__ out_lo,
    float* __restrict__ out_f,
    int Nin, int Nout, int fp32_in)
{
    constexpr int NTT   = NT / 32;           // nt tiles per warp (4 or 2)
    constexpr int NHALF = NT / 64;           // 16-col B slabs per warp (2 or 1)
    constexpr int SEGT  = NT / 8;            // times per loader thread (16 or 8)
    constexpr int BSZ   = NT * RS;           // one B buffer

    // smem layout: AH[2] | AL[2] | BH[2] | BL[2]
    extern __shared__ __align__(16) char smem[];
    const uint32_t su = (uint32_t)__cvta_generic_to_shared(smem);
    const uint32_t uAH = su;
    const uint32_t uAL = su + 2 * ASZ;
    const uint32_t uBH = su + 4 * ASZ;
    const uint32_t uBL = su + 4 * ASZ + 2 * BSZ;

    const int tid  = threadIdx.x;
    const int lane = tid & 31;
    const int wid  = tid >> 5;
    const int wm   = wid & 1;
    const int wn   = wid >> 1;
    const int m0   = blockIdx.y * 128;
    const int j0   = blockIdx.x * NT;

    float acc[4][NTT][4];
    #pragma unroll
    for (int a = 0; a < 4; a++)
        #pragma unroll
        for (int b = 0; b < NTT; b++)
            #pragma unroll
            for (int c = 0; c < 4; c++) acc[a][b][c] = 0.f;

    // ldmatrix per-lane source rows (verified mapping)
    const int a_row = lane & 15;
    const int a_cb  = lane >> 4;
    const int b_row = (lane & 7) + ((lane >> 4) << 3);
    const int b_cb  = (lane >> 3) & 1;

    // loader mapping
    const int l_arow = tid >> 1, l_ahalf = tid & 1;
    const int l_c = tid & 15, l_seg = tid >> 4;

    // ---- persistent prefetch registers ----
    uint4 pAh0, pAh1, pAl0, pAl1;
    uint32_t pBh[SEGT / 2], pBl[SEGT / 2];

    auto load_g = [&](int chunk) {
        const int k0 = chunk * 32;
        {
            size_t gofs = (size_t)(m0 + l_arow) * 512 + k0 + l_ahalf * 16;
            const uint4* ph = reinterpret_cast<const uint4*>(Whi + gofs);
            const uint4* pl = reinterpret_cast<const uint4*>(Wlo + gofs);
            pAh0 = ph[0]; pAh1 = ph[1];
            pAl0 = pl[0]; pAl1 = pl[1];
        }
        {
            const int ch = (k0 >> 1) + l_c;
            const int t  = 2 * j0 + l_seg * SEGT;
            if (fp32_in) {
                const float* p = reinterpret_cast<const float*>(in_hi) + (size_t)ch * Nin + t;
                if (t + SEGT - 1 < Nin) {
                    #pragma unroll
                    for (int q = 0; q < SEGT / 4; q++) {
                        float4 f = reinterpret_cast<const float4*>(p)[q];
                        split2(f.x, f.y, pBh[2 * q],     pBl[2 * q]);
                        split2(f.z, f.w, pBh[2 * q + 1], pBl[2 * q + 1]);
                    }
                } else {
                    #pragma unroll
                    for (int q = 0; q < SEGT / 2; q++) {
                        float f0 = (t + 2 * q     < Nin) ? p[2 * q]     : 0.f;
                        float f1 = (t + 2 * q + 1 < Nin) ? p[2 * q + 1] : 0.f;
                        split2(f0, f1, pBh[q], pBl[q]);
                    }
                }
            } else {
                const __nv_bfloat16* ph = reinterpret_cast<const __nv_bfloat16*>(in_hi) + (size_t)ch * Nin + t;
                const __nv_bfloat16* pl = in_lo + (size_t)ch * Nin + t;
                if (t + SEGT - 1 < Nin) {
                    #pragma unroll
                    for (int q = 0; q < SEGT / 8; q++) {
                        uint4 uh = reinterpret_cast<const uint4*>(ph)[q];
                        uint4 ul = reinterpret_cast<const uint4*>(pl)[q];
                        pBh[4 * q + 0] = uh.x; pBh[4 * q + 1] = uh.y;
                        pBh[4 * q + 2] = uh.z; pBh[4 * q + 3] = uh.w;
                        pBl[4 * q + 0] = ul.x; pBl[4 * q + 1] = ul.y;
                        pBl[4 * q + 2] = ul.z; pBl[4 * q + 3] = ul.w;
                    }
                } else {
                    #pragma unroll
                    for (int q = 0; q < SEGT / 2; q++) {
                        __nv_bfloat162 hp, lp;
                        hp.x = (t + 2 * q     < Nin) ? ph[2 * q]     : __nv_bfloat16(0.f);
                        hp.y = (t + 2 * q + 1 < Nin) ? ph[2 * q + 1] : __nv_bfloat16(0.f);
                        lp.x = (t + 2 * q     < Nin) ? pl[2 * q]     : __nv_bfloat16(0.f);
                        lp.y = (t + 2 * q + 1 < Nin) ? pl[2 * q + 1] : __nv_bfloat16(0.f);
                        pBh[q] = *reinterpret_cast<uint32_t*>(&hp);
                        pBl[q] = *reinterpret_cast<uint32_t*>(&lp);
                    }
                }
            }
        }
    };

    auto store_smem = [&](int buf) {
        char* base = smem;
        char* dh = base + buf * ASZ + l_arow * RS + l_ahalf * 32;
        char* dl = base + 2 * ASZ + buf * ASZ + l_arow * RS + l_ahalf * 32;
        reinterpret_cast<uint4*>(dh)[0] = pAh0;
        reinterpret_cast<uint4*>(dh)[1] = pAh1;
        reinterpret_cast<uint4*>(dl)[0] = pAl0;
        reinterpret_cast<uint4*>(dl)[1] = pAl1;
        char* dbh = base + 4 * ASZ + buf * BSZ + (l_seg * (SEGT / 2)) * RS + 4 * l_c;
        char* dbl = base + 4 * ASZ + 2 * BSZ + buf * BSZ + (l_seg * (SEGT / 2)) * RS + 4 * l_c;
        #pragma unroll
        for (int q = 0; q < SEGT / 2; q++) {
            *reinterpret_cast<uint32_t*>(dbh + q * RS) = pBh[q];
            *reinterpret_cast<uint32_t*>(dbl + q * RS) = pBl[q];
        }
    };

    // prologue: fill buf0, start prefetch of chunk1
    load_g(0);
    store_smem(0);
    load_g(1);
    __syncthreads();

    for (int chunk = 0; chunk < 16; chunk++) {
        const int buf = chunk & 1;
        const uint32_t aH = uAH + buf * ASZ;
        const uint32_t aL = uAL + buf * ASZ;
        const uint32_t bH = uBH + buf * BSZ;
        const uint32_t bL = uBL + buf * BSZ;

        // ---- compute: 2 k16 steps; all ldsm hoisted per step ----
        #pragma unroll
        for (int ks = 0; ks < 2; ks++) {
            uint32_t ah[4][4], al[4][4], bh[NTT][2], bl[NTT][2];
            #pragma unroll
            for (int mt = 0; mt < 4; mt++) {
                uint32_t ofs = (uint32_t)((wm * 64 + mt * 16 + a_row) * RS + ks * 32 + a_cb * 16);
                ldsm_x4(ah[mt], aH + ofs);
            }
            #pragma unroll
            for (int half = 0; half < NHALF; half++) {
                uint32_t ofs = (uint32_t)((wn * (NT / 4) + half * 16 + b_row) * RS + ks * 32 + b_cb * 16);
                uint32_t r[4];
                ldsm_x4(r, bH + ofs);
                bh[half * 2][0] = r[0]; bh[half * 2][1] = r[1];
                bh[half * 2 + 1][0] = r[2]; bh[half * 2 + 1][1] = r[3];
                ldsm_x4(r, bL + ofs);
                bl[half * 2][0] = r[0]; bl[half * 2][1] = r[1];
                bl[half * 2 + 1][0] = r[2]; bl[half * 2 + 1][1] = r[3];
            }
            #pragma unroll
            for (int mt = 0; mt < 4; mt++) {
                uint32_t ofs = (uint32_t)((wm * 64 + mt * 16 + a_row) * RS + ks * 32 + a_cb * 16);
                ldsm_x4(al[mt], aL + ofs);
            }
            #pragma unroll
            for (int mt = 0; mt < 4; mt++)
                #pragma unroll
                for (int nt = 0; nt < NTT; nt++) {
                    mma_bf16(acc[mt][nt], ah[mt], bh[nt]);
                    mma_bf16(acc[mt][nt], ah[mt], bl[nt]);
                }
            #pragma unroll
            for (int mt = 0; mt < 4; mt++)
                #pragma unroll
                for (int nt = 0; nt < NTT; nt++)
                    mma_bf16(acc[mt][nt], al[mt], bh[nt]);
        }

        // ---- stage next chunk into the other buffer ----
        if (chunk + 1 < 16) {
            store_smem((chunk + 1) & 1);
            if (chunk + 2 < 16) load_g(chunk + 2);
        }
        __syncthreads();
    }

    // ---- epilogue ----
    const int g = lane >> 2, tig = lane & 3;
    #pragma unroll
    for (int mt = 0; mt < 4; mt++) {
        const int mA = m0 + wm * 64 + mt * 16 + g;
        const int mB = mA + 8;
        const float bA = bias[mA], bB = bias[mB];
        #pragma unroll
        for (int nt = 0; nt < NTT; nt++) {
            const int col = j0 + wn * (NT / 4) + nt * 8 + 2 * tig;
            float v0 = tanhf(acc[mt][nt][0] + bA);
            float v1 = tanhf(acc[mt][nt][1] + bA);
            float v2 = tanhf(acc[mt][nt][2] + bB);
            float v3 = tanhf(acc[mt][nt][3] + bB);
            if (out_f) {
                if (col == 0) { out_f[mA] = v0; out_f[mB] = v2; }
            } else if (col < Nout) {
                uint32_t h, l;
                split2(v0, v1, h, l);
                *reinterpret_cast<uint32_t*>(out_hi + (size_t)mA * Nout + col) = h;
                *reinterpret_cast<uint32_t*>(out_lo + (size_t)mA * Nout + col) = l;
                split2(v2, v3, h, l);
                *reinterpret_cast<uint32_t*>(out_hi + (size_t)mB * Nout + col) = h;
                *reinterpret_cast<uint32_t*>(out_lo + (size_t)mB * Nout + col) = l;
            }
        }
    }
}

// ---------------- host ----------------
extern "C" void kernel_launch(void* const* d_in, const int* in_sizes, int n_in,
                              void* d_out, int out_size)
{
    const float* x = (const float*)d_in[0];
    const float* W = (const float*)d_in[1];
    const float* b = (const float*)d_in[2];

    __nv_bfloat16 *ahi, *alo, *bhi, *blo, *whi, *wlo;
    cudaGetSymbolAddress((void**)&ahi, g_ahi);
    cudaGetSymbolAddress((void**)&alo, g_alo);
    cudaGetSymbolAddress((void**)&bhi, g_bhi);
    cudaGetSymbolAddress((void**)&blo, g_blo);
    cudaGetSymbolAddress((void**)&whi, g_whi);
    cudaGetSymbolAddress((void**)&wlo, g_wlo);

    const int smem128 = 4 * ASZ + 4 * 128 * RS;   // 81920
    const int smem64  = 4 * ASZ + 4 * 64 * RS;    // 61440
    cudaFuncSetAttribute(layer_hmma<128>, cudaFuncAttributeMaxDynamicSharedMemorySize, smem128);
    cudaFuncSetAttribute(layer_hmma<64>,  cudaFuncAttributeMaxDynamicSharedMemorySize, smem64);

    const int nW = 16 * 256 * 512;
    prep_w<<<(nW + 255) / 256, 256>>>(W, whi, wlo, nW);

    int Nin = 65536;
    const void* cur_hi = (const void*)x;
    const __nv_bfloat16* cur_lo = nullptr;
    int fp32_in = 1;

    for (int i = 0; i < 16; i++) {
        int Nout = Nin >> 1;
        __nv_bfloat16* ohi = (i & 1) ? bhi : ahi;
        __nv_bfloat16* olo = (i & 1) ? blo : alo;
        float* of = (i == 15) ? (float*)d_out : nullptr;
        if (Nout >= 16384) {
            dim3 grid((Nout + 127) / 128, 2);
            layer_hmma<128><<<grid, 256, smem128>>>(cur_hi, cur_lo,
                                      whi + (size_t)i * 256 * 512,
                                      wlo + (size_t)i * 256 * 512,
                                      b + i * 256,
                                      ohi, olo, of, Nin, Nout, fp32_in);
        } else {
            dim3 grid((Nout + 63) / 64, 2);
            layer_hmma<64><<<grid, 256, smem64>>>(cur_hi, cur_lo,
                                      whi + (size_t)i * 256 * 512,
                                      wlo + (size_t)i * 256 * 512,
                                      b + i * 256,
                                      ohi, olo, of, Nin, Nout, fp32_in);
        }
        cur_hi = (const void*)ohi;
        cur_lo = olo;
        fp32_in = 0;
        Nin = Nout;
    }
}

// round 13
// speedup vs baseline: 1.5932x; 1.3227x over previous
#include <cuda_runtime.h>
#include <cuda_bf16.h>
#include <cstdint>
#include <math.h>

// ============================================================
// bf16-split GEMM per layer via mma.sync (HMMA).
//   layer i: out[c,j] = tanh( sum_k W[c,k]*B[k,j] + bias[c] )
//   B[k][j] = in[k>>1][2j + (k&1)]   (compacted dilated conv)
//   fp32 ~= bf16 hi+lo:  A*B ~= Ah*Bh + Ah*Bl + Al*Bh
// R13: R12 + split-K (S=2/4) for underfilled layers:
//   GEMM kernel gains chunk bounds [kb,ke) + fp32 partial-store
//   mode (blockIdx.z = split). Reduce kernel: sum partials +
//   bias + tanh + hi/lo split. Spreads serial K-chain over
//   idle SMs -> per-layer latency / S.
// ============================================================

#define RS 80   // smem row stride in bytes (64B payload + pad)
#define ASZ (128 * RS)          // one A buffer (10240 B)

// ---------------- scratch ----------------
__device__ __nv_bfloat16 g_ahi[256 * 32768];
__device__ __nv_bfloat16 g_alo[256 * 32768];
__device__ __nv_bfloat16 g_bhi[256 * 16384];
__device__ __nv_bfloat16 g_blo[256 * 16384];
__device__ __nv_bfloat16 g_whi[16 * 256 * 512];
__device__ __nv_bfloat16 g_wlo[16 * 256 * 512];
__device__ float g_part[4 * 256 * 4096];   // split-K partials (16MB)

// ---------------- helpers ----------------
__device__ __forceinline__ void ldsm_x4(uint32_t* r, uint32_t addr) {
    asm volatile("ldmatrix.sync.aligned.m8n8.x4.shared.b16 {%0,%1,%2,%3}, [%4];"
        : "=r"(r[0]), "=r"(r[1]), "=r"(r[2]), "=r"(r[3]) : "r"(addr));
}

__device__ __forceinline__ void mma_bf16(float* c, const uint32_t* a, const uint32_t* b) {
    asm volatile(
        "mma.sync.aligned.m16n8k16.row.col.f32.bf16.bf16.f32 "
        "{%0,%1,%2,%3}, {%4,%5,%6,%7}, {%8,%9}, {%0,%1,%2,%3};"
        : "+f"(c[0]), "+f"(c[1]), "+f"(c[2]), "+f"(c[3])
        : "r"(a[0]), "r"(a[1]), "r"(a[2]), "r"(a[3]), "r"(b[0]), "r"(b[1]));
}

__device__ __forceinline__ void split2(float x, float y, uint32_t& h, uint32_t& l) {
    __nv_bfloat16 hx = __float2bfloat16(x);
    __nv_bfloat16 hy = __float2bfloat16(y);
    __nv_bfloat162 hp; hp.x = hx; hp.y = hy;
    __nv_bfloat162 lp;
    lp.x = __float2bfloat16(x - __bfloat162float(hx));
    lp.y = __float2bfloat16(y - __bfloat162float(hy));
    h = *reinterpret_cast<uint32_t*>(&hp);
    l = *reinterpret_cast<uint32_t*>(&lp);
}

// ---------------- weight hi/lo split ----------------
__global__ void prep_w(const float* __restrict__ W,
                       __nv_bfloat16* __restrict__ hi,
                       __nv_bfloat16* __restrict__ lo, int n) {
    int i = blockIdx.x * blockDim.x + threadIdx.x;
    if (i < n) {
        float v = W[i];
        __nv_bfloat16 h = __float2bfloat16(v);
        hi[i] = h;
        lo[i] = __float2bfloat16(v - __bfloat162float(h));
    }
}

// ---------------- split-K reduce: sum + bias + tanh + split ----------------
__global__ void reduce_k(const float* __restrict__ gpart, int S,
                         const float* __restrict__ bias, int Nout,
                         __nv_bfloat16* __restrict__ out_hi,
                         __nv_bfloat16* __restrict__ out_lo,
                         float* __restrict__ out_f) {
    const int stride = 256 * Nout;
    if (out_f) {                               // final layer: Nout == 1
        int c = blockIdx.x * blockDim.x + threadIdx.x;
        if (c < 256) {
            float s = bias[c];
            for (int q = 0; q < S; q++) s += gpart[q * stride + c];
            out_f[c] = tanhf(s);
        }
        return;
    }
    const int np = Nout >> 1;                  // pairs per channel
    int idx = blockIdx.x * blockDim.x + threadIdx.x;
    if (idx < 256 * np) {
        int c = idx / np, jp = idx % np, j = 2 * jp;
        float s0 = bias[c], s1 = s0;
        const float* p = gpart + c * Nout + j;
        for (int q = 0; q < S; q++) {
            s0 += p[q * stride];
            s1 += p[q * stride + 1];
        }
        float v0 = tanhf(s0), v1 = tanhf(s1);
        uint32_t h, l;
        split2(v0, v1, h, l);
        *reinterpret_cast<uint32_t*>(out_hi + (size_t)c * Nout + j) = h;
        *reinterpret_cast<uint32_t*>(out_lo + (size_t)c * Nout + j) = l;
    }
}

// ---------------- per-layer GEMM kernel ----------------
// CTA: 256 threads = 8 warps in 2(M) x 4(N); tile 128 x NT, BK=32.
// Chunks [kb, ke). gpart != null -> fp32 partial store (split blockIdx.z).
template<int NT>
__global__ __launch_bounds__(256) void layer_hmma(
    const void* __restrict__ in_hi,
    const __nv_bfloat16* __restrict__ in_lo,
    const __nv_bfloat16* __restrict__ Whi,   // 256 x 512
    const __nv_bfloat16* __restrict__ Wlo,
    const float* __restrict__ bias,
    __nv_bfloat16* __restrict__ out_hi,
    __nv_bfloat16* __restrict__ out_lo,
    float* __restrict__ out_f,
    float* __restrict__ gpart,
    int Nin, int Nout, int fp32_in, int cs)   // cs = chunks per split
{
    constexpr int NTT   = NT / 32;
    constexpr int NHALF = NT / 64;
    constexpr int SEGT  = NT / 8;
    constexpr int BSZ   = NT * RS;

    extern __shared__ __align__(16) char smem[];
    const uint32_t su = (uint32_t)__cvta_generic_to_shared(smem);
    const uint32_t uAH = su;
    const uint32_t uAL = su + 2 * ASZ;
    const uint32_t uBH = su + 4 * ASZ;
    const uint32_t uBL = su + 4 * ASZ + 2 * BSZ;

    const int tid  = threadIdx.x;
    const int lane = tid & 31;
    const int wid  = tid >> 5;
    const int wm   = wid & 1;
    const int wn   = wid >> 1;
    const int m0   = blockIdx.y * 128;
    const int j0   = blockIdx.x * NT;
    const int kb   = blockIdx.z * cs;
    const int ke   = kb + cs;

    float acc[4][NTT][4];
    #pragma unroll
    for (int a = 0; a < 4; a++)
        #pragma unroll
        for (int b = 0; b < NTT; b++)
            #pragma unroll
            for (int c = 0; c < 4; c++) acc[a][b][c] = 0.f;

    const int a_row = lane & 15;
    const int a_cb  = lane >> 4;
    const int b_row = (lane & 7) + ((lane >> 4) << 3);
    const int b_cb  = (lane >> 3) & 1;

    const int l_arow = tid >> 1, l_ahalf = tid & 1;
    const int l_c = tid & 15, l_seg = tid >> 4;

    uint4 pAh0, pAh1, pAl0, pAl1;
    uint32_t pBh[SEGT / 2], pBl[SEGT / 2];

    auto load_g = [&](int chunk) {
        const int k0 = chunk * 32;
        {
            size_t gofs = (size_t)(m0 + l_arow) * 512 + k0 + l_ahalf * 16;
            const uint4* ph = reinterpret_cast<const uint4*>(Whi + gofs);
            const uint4* pl = reinterpret_cast<const uint4*>(Wlo + gofs);
            pAh0 = ph[0]; pAh1 = ph[1];
            pAl0 = pl[0]; pAl1 = pl[1];
        }
        {
            const int ch = (k0 >> 1) + l_c;
            const int t  = 2 * j0 + l_seg * SEGT;
            if (fp32_in) {
                const float* p = reinterpret_cast<const float*>(in_hi) + (size_t)ch * Nin + t;
                if (t + SEGT - 1 < Nin) {
                    #pragma unroll
                    for (int q = 0; q < SEGT / 4; q++) {
                        float4 f = reinterpret_cast<const float4*>(p)[q];
                        split2(f.x, f.y, pBh[2 * q],     pBl[2 * q]);
                        split2(f.z, f.w, pBh[2 * q + 1], pBl[2 * q + 1]);
                    }
                } else {
                    #pragma unroll
                    for (int q = 0; q < SEGT / 2; q++) {
                        float f0 = (t + 2 * q     < Nin) ? p[2 * q]     : 0.f;
                        float f1 = (t + 2 * q + 1 < Nin) ? p[2 * q + 1] : 0.f;
                        split2(f0, f1, pBh[q], pBl[q]);
                    }
                }
            } else {
                const __nv_bfloat16* ph = reinterpret_cast<const __nv_bfloat16*>(in_hi) + (size_t)ch * Nin + t;
                const __nv_bfloat16* pl = in_lo + (size_t)ch * Nin + t;
                if (t + SEGT - 1 < Nin) {
                    #pragma unroll
                    for (int q = 0; q < SEGT / 8; q++) {
                        uint4 uh = reinterpret_cast<const uint4*>(ph)[q];
                        uint4 ul = reinterpret_cast<const uint4*>(pl)[q];
                        pBh[4 * q + 0] = uh.x; pBh[4 * q + 1] = uh.y;
                        pBh[4 * q + 2] = uh.z; pBh[4 * q + 3] = uh.w;
                        pBl[4 * q + 0] = ul.x; pBl[4 * q + 1] = ul.y;
                        pBl[4 * q + 2] = ul.z; pBl[4 * q + 3] = ul.w;
                    }
                } else {
                    #pragma unroll
                    for (int q = 0; q < SEGT / 2; q++) {
                        __nv_bfloat162 hp, lp;
                        hp.x = (t + 2 * q     < Nin) ? ph[2 * q]     : __nv_bfloat16(0.f);
                        hp.y = (t + 2 * q + 1 < Nin) ? ph[2 * q + 1] : __nv_bfloat16(0.f);
                        lp.x = (t + 2 * q     < Nin) ? pl[2 * q]     : __nv_bfloat16(0.f);
                        lp.y = (t + 2 * q + 1 < Nin) ? pl[2 * q + 1] : __nv_bfloat16(0.f);
                        pBh[q] = *reinterpret_cast<uint32_t*>(&hp);
                        pBl[q] = *reinterpret_cast<uint32_t*>(&lp);
                    }
                }
            }
        }
    };

    auto store_smem = [&](int buf) {
        char* base = smem;
        char* dh = base + buf * ASZ + l_arow * RS + l_ahalf * 32;
        char* dl = base + 2 * ASZ + buf * ASZ + l_arow * RS + l_ahalf * 32;
        reinterpret_cast<uint4*>(dh)[0] = pAh0;
        reinterpret_cast<uint4*>(dh)[1] = pAh1;
        reinterpret_cast<uint4*>(dl)[0] = pAl0;
        reinterpret_cast<uint4*>(dl)[1] = pAl1;
        char* dbh = base + 4 * ASZ + buf * BSZ + (l_seg * (SEGT / 2)) * RS + 4 * l_c;
        char* dbl = base + 4 * ASZ + 2 * BSZ + buf * BSZ + (l_seg * (SEGT / 2)) * RS + 4 * l_c;
        #pragma unroll
        for (int q = 0; q < SEGT / 2; q++) {
            *reinterpret_cast<uint32_t*>(dbh + q * RS) = pBh[q];
            *reinterpret_cast<uint32_t*>(dbl + q * RS) = pBl[q];
        }
    };

    load_g(kb);
    store_smem(0);
    if (kb + 1 < ke) load_g(kb + 1);
    __syncthreads();

    for (int chunk = kb; chunk < ke; chunk++) {
        const int buf = (chunk - kb) & 1;
        const uint32_t aH = uAH + buf * ASZ;
        const uint32_t aL = uAL + buf * ASZ;
        const uint32_t bH = uBH + buf * BSZ;
        const uint32_t bL = uBL + buf * BSZ;

        #pragma unroll
        for (int ks = 0; ks < 2; ks++) {
            uint32_t ah[4][4], al[4][4], bh[NTT][2], bl[NTT][2];
            #pragma unroll
            for (int mt = 0; mt < 4; mt++) {
                uint32_t ofs = (uint32_t)((wm * 64 + mt * 16 + a_row) * RS + ks * 32 + a_cb * 16);
                ldsm_x4(ah[mt], aH + ofs);
            }
            #pragma unroll
            for (int half = 0; half < NHALF; half++) {
                uint32_t ofs = (uint32_t)((wn * (NT / 4) + half * 16 + b_row) * RS + ks * 32 + b_cb * 16);
                uint32_t r[4];
                ldsm_x4(r, bH + ofs);
                bh[half * 2][0] = r[0]; bh[half * 2][1] = r[1];
                bh[half * 2 + 1][0] = r[2]; bh[half * 2 + 1][1] = r[3];
                ldsm_x4(r, bL + ofs);
                bl[half * 2][0] = r[0]; bl[half * 2][1] = r[1];
                bl[half * 2 + 1][0] = r[2]; bl[half * 2 + 1][1] = r[3];
            }
            #pragma unroll
            for (int mt = 0; mt < 4; mt++) {
                uint32_t ofs = (uint32_t)((wm * 64 + mt * 16 + a_row) * RS + ks * 32 + a_cb * 16);
                ldsm_x4(al[mt], aL + ofs);
            }
            #pragma unroll
            for (int mt = 0; mt < 4; mt++)
                #pragma unroll
                for (int nt = 0; nt < NTT; nt++) {
                    mma_bf16(acc[mt][nt], ah[mt], bh[nt]);
                    mma_bf16(acc[mt][nt], ah[mt], bl[nt]);
                }
            #pragma unroll
            for (int mt = 0; mt < 4; mt++)
                #pragma unroll
                for (int nt = 0; nt < NTT; nt++)
                    mma_bf16(acc[mt][nt], al[mt], bh[nt]);
        }

        if (chunk + 1 < ke) {
            store_smem((chunk + 1 - kb) & 1);
            if (chunk + 2 < ke) load_g(chunk + 2);
        }
        __syncthreads();
    }

    // ---- epilogue ----
    const int g = lane >> 2, tig = lane & 3;
    if (gpart) {
        // raw fp32 partial store (no bias/tanh)
        float* gp = gpart + (size_t)blockIdx.z * 256 * Nout;
        #pragma unroll
        for (int mt = 0; mt < 4; mt++) {
            const int mA = m0 + wm * 64 + mt * 16 + g;
            const int mB = mA + 8;
            #pragma unroll
            for (int nt = 0; nt < NTT; nt++) {
                const int col = j0 + wn * (NT / 4) + nt * 8 + 2 * tig;
                if (col < Nout) {
                    gp[(size_t)mA * Nout + col] = acc[mt][nt][0];
                    gp[(size_t)mB * Nout + col] = acc[mt][nt][2];
                    if (col + 1 < Nout) {
                        gp[(size_t)mA * Nout + col + 1] = acc[mt][nt][1];
                        gp[(size_t)mB * Nout + col + 1] = acc[mt][nt][3];
                    }
                }
            }
        }
        return;
    }
    #pragma unroll
    for (int mt = 0; mt < 4; mt++) {
        const int mA = m0 + wm * 64 + mt * 16 + g;
        const int mB = mA + 8;
        const float bA = bias[mA], bB = bias[mB];
        #pragma unroll
        for (int nt = 0; nt < NTT; nt++) {
            const int col = j0 + wn * (NT / 4) + nt * 8 + 2 * tig;
            float v0 = tanhf(acc[mt][nt][0] + bA);
            float v1 = tanhf(acc[mt][nt][1] + bA);
            float v2 = tanhf(acc[mt][nt][2] + bB);
            float v3 = tanhf(acc[mt][nt][3] + bB);
            if (out_f) {
                if (col == 0) { out_f[mA] = v0; out_f[mB] = v2; }
            } else if (col < Nout) {
                uint32_t h, l;
                split2(v0, v1, h, l);
                *reinterpret_cast<uint32_t*>(out_hi + (size_t)mA * Nout + col) = h;
                *reinterpret_cast<uint32_t*>(out_lo + (size_t)mA * Nout + col) = l;
                split2(v2, v3, h, l);
                *reinterpret_cast<uint32_t*>(out_hi + (size_t)mB * Nout + col) = h;
                *reinterpret_cast<uint32_t*>(out_lo + (size_t)mB * Nout + col) = l;
            }
        }
    }
}

// ---------------- host ----------------
extern "C" void kernel_launch(void* const* d_in, const int* in_sizes, int n_in,
                              void* d_out, int out_size)
{
    const float* x = (const float*)d_in[0];
    const float* W = (const float*)d_in[1];
    const float* b = (const float*)d_in[2];

    __nv_bfloat16 *ahi, *alo, *bhi, *blo, *whi, *wlo;
    float* gpart;
    cudaGetSymbolAddress((void**)&ahi, g_ahi);
    cudaGetSymbolAddress((void**)&alo, g_alo);
    cudaGetSymbolAddress((void**)&bhi, g_bhi);
    cudaGetSymbolAddress((void**)&blo, g_blo);
    cudaGetSymbolAddress((void**)&whi, g_whi);
    cudaGetSymbolAddress((void**)&wlo, g_wlo);
    cudaGetSymbolAddress((void**)&gpart, g_part);

    const int smem128 = 4 * ASZ + 4 * 128 * RS;   // 81920
    const int smem64  = 4 * ASZ + 4 * 64 * RS;    // 61440
    cudaFuncSetAttribute(layer_hmma<128>, cudaFuncAttributeMaxDynamicSharedMemorySize, smem128);
    cudaFuncSetAttribute(layer_hmma<64>,  cudaFuncAttributeMaxDynamicSharedMemorySize, smem64);

    const int nW = 16 * 256 * 512;
    prep_w<<<(nW + 255) / 256, 256>>>(W, whi, wlo, nW);

    int Nin = 65536;
    const void* cur_hi = (const void*)x;
    const __nv_bfloat16* cur_lo = nullptr;
    int fp32_in = 1;

    for (int i = 0; i < 16; i++) {
        int Nout = Nin >> 1;
        __nv_bfloat16* ohi = (i & 1) ? bhi : ahi;
        __nv_bfloat16* olo = (i & 1) ? blo : alo;
        float* of = (i == 15) ? (float*)d_out : nullptr;

        if (Nout >= 16384) {
            dim3 grid((Nout + 127) / 128, 2);
            layer_hmma<128><<<grid, 256, smem128>>>(cur_hi, cur_lo,
                whi + (size_t)i * 256 * 512, wlo + (size_t)i * 256 * 512,
                b + i * 256, ohi, olo, of, nullptr, Nin, Nout, fp32_in, 16);
        } else {
            int gx = (Nout + 63) / 64;
            int base = gx * 2;
            int S = 1;
            if (base < 256) S = (256 / base >= 4) ? 4 : 2;   // split-K factor
            if (S == 1) {
                dim3 grid(gx, 2);
                layer_hmma<64><<<grid, 256, smem64>>>(cur_hi, cur_lo,
                    whi + (size_t)i * 256 * 512, wlo + (size_t)i * 256 * 512,
                    b + i * 256, ohi, olo, of, nullptr, Nin, Nout, fp32_in, 16);
            } else {
                dim3 grid(gx, 2, S);
                layer_hmma<64><<<grid, 256, smem64>>>(cur_hi, cur_lo,
                    whi + (size_t)i * 256 * 512, wlo + (size_t)i * 256 * 512,
                    b + i * 256, nullptr, nullptr, nullptr, gpart,
                    Nin, Nout, fp32_in, 16 / S);
                int work = (i == 15) ? 256 : 256 * (Nout >> 1);
                reduce_k<<<(work + 255) / 256, 256>>>(gpart, S, b + i * 256,
                                                      Nout, ohi, olo, of);
            }
        }
        cur_hi = (const void*)ohi;
        cur_lo = olo;
        fp32_in = 0;
        Nin = Nout;
    }
}